// round 8
// baseline (speedup 1.0000x reference)
#include <cuda_runtime.h>

// ---------------------------------------------------------------------------
// 2-layer GCN, normalization factored; aggregation done in 2-dim feature space
// (Â(xW1) = (Âx)W1). Edge passes: 8 edges/thread, batched index loads ->
// batched gathers -> batched REDs for max MLP at the L1tex queue.
// ---------------------------------------------------------------------------

#define N_MAX 100000
#define F1 16

__device__ float2 g_xs  [N_MAX];   // dinv[i] * x[i]
__device__ float2 g_acc1[N_MAX];   // layer-1 edge sum (2-dim space)
__device__ float2 g_h2s [N_MAX];   // dinv[i] * (relu(l1) @ W2)
__device__ float2 g_acc2[N_MAX];   // layer-2 edge sum
__device__ float  g_deg [N_MAX];
__device__ float  g_dinv[N_MAX];
__device__ int    g_is64;          // 1 if edge_index is int64

// dtype probe: int64 indices < 1e5 -> every odd 32-bit word is 0.
__global__ void k_detect(const unsigned int* __restrict__ w, int nwords) {
    __shared__ int nz;
    if (threadIdx.x == 0) nz = 0;
    __syncthreads();
    for (int i = threadIdx.x; i < 4096; i += blockDim.x) {
        int idx = 2 * i + 1;
        if (idx < nwords && w[idx] != 0u) nz = 1;
    }
    __syncthreads();
    if (threadIdx.x == 0) g_is64 = (nz == 0);
}

__global__ void k_init(int n) {
    int i = blockIdx.x * blockDim.x + threadIdx.x;
    if (i >= n) return;
    g_deg[i] = 1.0f;                       // self loop
    float2 z = make_float2(0.f, 0.f);
    g_acc1[i] = z;
    g_acc2[i] = z;
}

// degree count at targets, 8 edges/thread
__global__ void k_deg(const void* __restrict__ ei, int E) {
    int t = blockIdx.x * blockDim.x + threadIdx.x;
    int base = t * 8;
    if (base >= E) return;
    if (!g_is64) {
        const int* dst = (const int*)ei + E;
        if (base + 8 <= E) {
            int4 d0 = *reinterpret_cast<const int4*>(dst + base);
            int4 d1 = *reinterpret_cast<const int4*>(dst + base + 4);
            atomicAdd(&g_deg[d0.x], 1.0f);
            atomicAdd(&g_deg[d0.y], 1.0f);
            atomicAdd(&g_deg[d0.z], 1.0f);
            atomicAdd(&g_deg[d0.w], 1.0f);
            atomicAdd(&g_deg[d1.x], 1.0f);
            atomicAdd(&g_deg[d1.y], 1.0f);
            atomicAdd(&g_deg[d1.z], 1.0f);
            atomicAdd(&g_deg[d1.w], 1.0f);
        } else {
            for (int e = base; e < E; e++) atomicAdd(&g_deg[dst[e]], 1.0f);
        }
    } else {
        const long long* dst = (const long long*)ei + E;
        int end = min(base + 8, E);
        for (int e = base; e < end; e++) atomicAdd(&g_deg[(int)dst[e]], 1.0f);
    }
}

// dinv + pre-scaled features
__global__ void k_pre(const float* __restrict__ x, int n) {
    int i = blockIdx.x * blockDim.x + threadIdx.x;
    if (i >= n) return;
    float di = rsqrtf(g_deg[i]);
    g_dinv[i] = di;
    float2 xv = reinterpret_cast<const float2*>(x)[i];
    g_xs[i] = make_float2(di * xv.x, di * xv.y);
}

// 2-dim scatter: acc[dst] += val[src], 8 edges/thread.
// Index loads first, then all gathers, then all REDs (MLP=8).
__device__ __forceinline__ void scat2d(const void* ei, int E,
                                       const float2* __restrict__ val,
                                       float2* __restrict__ acc) {
    int t = blockIdx.x * blockDim.x + threadIdx.x;
    int base = t * 8;
    if (base >= E) return;
    if (!g_is64) {
        const int* sp = (const int*)ei;
        const int* dp = sp + E;
        if (base + 8 <= E) {
            int4 s0 = *reinterpret_cast<const int4*>(sp + base);
            int4 s1 = *reinterpret_cast<const int4*>(sp + base + 4);
            int4 d0 = *reinterpret_cast<const int4*>(dp + base);
            int4 d1 = *reinterpret_cast<const int4*>(dp + base + 4);
            float2 v0 = val[s0.x];
            float2 v1 = val[s0.y];
            float2 v2 = val[s0.z];
            float2 v3 = val[s0.w];
            float2 v4 = val[s1.x];
            float2 v5 = val[s1.y];
            float2 v6 = val[s1.z];
            float2 v7 = val[s1.w];
            atomicAdd(&acc[d0.x], v0);
            atomicAdd(&acc[d0.y], v1);
            atomicAdd(&acc[d0.z], v2);
            atomicAdd(&acc[d0.w], v3);
            atomicAdd(&acc[d1.x], v4);
            atomicAdd(&acc[d1.y], v5);
            atomicAdd(&acc[d1.z], v6);
            atomicAdd(&acc[d1.w], v7);
        } else {
            for (int e = base; e < E; e++) atomicAdd(&acc[dp[e]], val[sp[e]]);
        }
    } else {
        const long long* sp = (const long long*)ei;
        const long long* dp = sp + E;
        int end = min(base + 8, E);
        for (int e = base; e < end; e++)
            atomicAdd(&acc[(int)dp[e]], val[(int)sp[e]]);
    }
}

__global__ void k_scat1(const void* __restrict__ ei, int E) {
    scat2d(ei, E, g_xs, g_acc1);
}
__global__ void k_scat2(const void* __restrict__ ei, int E) {
    scat2d(ei, E, g_h2s, g_acc2);
}

// finalize layer 1: project aggregated 2-dim -> 16 -> relu -> @W2 -> pre-scale
__global__ void k_fin1(const float* __restrict__ W1,
                       const float* __restrict__ b1,
                       const float* __restrict__ W2, int n) {
    __shared__ float w1[32];   // [2,16] row-major
    __shared__ float w2[32];   // [16,2] row-major
    __shared__ float bb[F1];
    if (threadIdx.x < 32) { w1[threadIdx.x] = W1[threadIdx.x];
                            w2[threadIdx.x] = W2[threadIdx.x]; }
    if (threadIdx.x < F1)   bb[threadIdx.x] = b1[threadIdx.x];
    __syncthreads();
    int i = blockIdx.x * blockDim.x + threadIdx.x;
    if (i >= n) return;
    float di = g_dinv[i];
    float2 a  = g_acc1[i];
    float2 xs = g_xs[i];
    float t0 = di * (a.x + xs.x);
    float t1 = di * (a.y + xs.y);
    float o0 = 0.f, o1 = 0.f;
#pragma unroll
    for (int j = 0; j < F1; j++) {
        float r = fmaxf(t0 * w1[j] + t1 * w1[F1 + j] + bb[j], 0.f);
        o0 += r * w2[2 * j];
        o1 += r * w2[2 * j + 1];
    }
    g_h2s[i] = make_float2(di * o0, di * o1);
}

// finalize layer 2 + log_softmax
__global__ void k_fin2(const float* __restrict__ b2,
                       float* __restrict__ out, int n) {
    int i = blockIdx.x * blockDim.x + threadIdx.x;
    if (i >= n) return;
    float di = g_dinv[i];
    float2 a = g_acc2[i];
    float2 h = g_h2s[i];
    float o0 = di * (a.x + h.x) + b2[0];
    float o1 = di * (a.y + h.y) + b2[1];
    float m = fmaxf(o0, o1);
    float lse = m + logf(expf(o0 - m) + expf(o1 - m));
    reinterpret_cast<float2*>(out)[i] = make_float2(o0 - lse, o1 - lse);
}

extern "C" void kernel_launch(void* const* d_in, const int* in_sizes, int n_in,
                              void* d_out, int out_size) {
    const float* x  = (const float*)d_in[0];
    const void*  ei = d_in[1];
    const float* W1 = (const float*)d_in[2];
    const float* b1 = (const float*)d_in[3];
    const float* W2 = (const float*)d_in[4];
    const float* b2 = (const float*)d_in[5];
    float*       out = (float*)d_out;

    int n = in_sizes[0] / 2;        // [n, 2]
    int E = in_sizes[1] / 2;        // [2, E]

    const int TBN = 256;
    const int TBE = 512;
    int gn  = (n + TBN - 1) / TBN;
    int ge8 = ((E + 7) / 8 + TBE - 1) / TBE;

    k_detect<<<1, 256>>>((const unsigned int*)ei, in_sizes[1]);
    k_init  <<<gn, TBN>>>(n);
    k_deg   <<<ge8, TBE>>>(ei, E);
    k_pre   <<<gn, TBN>>>(x, n);
    k_scat1 <<<ge8, TBE>>>(ei, E);
    k_fin1  <<<gn, TBN>>>(W1, b1, W2, n);
    k_scat2 <<<ge8, TBE>>>(ei, E);
    k_fin2  <<<gn, TBN>>>(b2, out, n);
}

// round 10
// speedup vs baseline: 1.0197x; 1.0197x over previous
#include <cuda_runtime.h>

// ---------------------------------------------------------------------------
// 2-layer GCN, normalization factored; aggregation done in 2-dim feature space
// (Â(xW1) = (Âx)W1).  Edge passes at the L2 random-sector roofline:
// 4 edges/thread, int4 index loads, float2 vector REDs (R5 best config).
// Init via cudaMemsetAsync; self-loop folded into rsqrt(deg+1).
// ---------------------------------------------------------------------------

#define N_MAX 100000
#define F1 16

__device__ float2 g_xs  [N_MAX];   // dinv[i] * x[i]
__device__ float2 g_acc1[N_MAX];   // layer-1 edge sum (2-dim space)
__device__ float2 g_h2s [N_MAX];   // dinv[i] * (relu(l1) @ W2)
__device__ float2 g_acc2[N_MAX];   // layer-2 edge sum
__device__ float  g_deg [N_MAX];   // edge-only degree (self-loop added later)
__device__ float  g_dinv[N_MAX];
__device__ int    g_is64;          // 1 if edge_index is int64

// dtype probe: int64 indices < 1e5 -> every odd 32-bit word is 0.
__global__ void k_detect(const unsigned int* __restrict__ w, int nwords) {
    __shared__ int nz;
    if (threadIdx.x == 0) nz = 0;
    __syncthreads();
    for (int i = threadIdx.x; i < 4096; i += blockDim.x) {
        int idx = 2 * i + 1;
        if (idx < nwords && w[idx] != 0u) nz = 1;
    }
    __syncthreads();
    if (threadIdx.x == 0) g_is64 = (nz == 0);
}

// degree count at targets, 4 edges/thread via int4
__global__ void k_deg(const void* __restrict__ ei, int E) {
    int t = blockIdx.x * blockDim.x + threadIdx.x;
    int base = t * 4;
    if (base >= E) return;
    if (!g_is64) {
        const int* dst = (const int*)ei + E;
        if (base + 4 <= E) {
            int4 d = *reinterpret_cast<const int4*>(dst + base);
            atomicAdd(&g_deg[d.x], 1.0f);
            atomicAdd(&g_deg[d.y], 1.0f);
            atomicAdd(&g_deg[d.z], 1.0f);
            atomicAdd(&g_deg[d.w], 1.0f);
        } else {
            for (int e = base; e < E; e++) atomicAdd(&g_deg[dst[e]], 1.0f);
        }
    } else {
        const long long* dst = (const long long*)ei + E;
        int end = min(base + 4, E);
        for (int e = base; e < end; e++) atomicAdd(&g_deg[(int)dst[e]], 1.0f);
    }
}

// dinv + pre-scaled features, 2 nodes/thread (float4 I/O)
__global__ void k_pre(const float* __restrict__ x, int n) {
    int t = blockIdx.x * blockDim.x + threadIdx.x;
    int i = t * 2;
    if (i >= n) return;
    if (i + 2 <= n) {
        float2 dg = *reinterpret_cast<const float2*>(g_deg + i);
        float d0 = rsqrtf(dg.x + 1.0f);        // +1 = self loop
        float d1 = rsqrtf(dg.y + 1.0f);
        *reinterpret_cast<float2*>(g_dinv + i) = make_float2(d0, d1);
        float4 xv = *reinterpret_cast<const float4*>(x + i * 2);
        float4 o = make_float4(d0 * xv.x, d0 * xv.y, d1 * xv.z, d1 * xv.w);
        *reinterpret_cast<float4*>(&g_xs[i]) = o;
    } else {
        float di = rsqrtf(g_deg[i] + 1.0f);
        g_dinv[i] = di;
        float2 xv = reinterpret_cast<const float2*>(x)[i];
        g_xs[i] = make_float2(di * xv.x, di * xv.y);
    }
}

// 2-dim scatter: acc[dst] += val[src], 4 edges/thread (R5 best config)
__device__ __forceinline__ void scat2d(const void* ei, int E,
                                       const float2* __restrict__ val,
                                       float2* __restrict__ acc) {
    int t = blockIdx.x * blockDim.x + threadIdx.x;
    int base = t * 4;
    if (base >= E) return;
    if (!g_is64) {
        const int* sp = (const int*)ei;
        const int* dp = sp + E;
        if (base + 4 <= E) {
            int4 s = *reinterpret_cast<const int4*>(sp + base);
            int4 d = *reinterpret_cast<const int4*>(dp + base);
            float2 v0 = val[s.x], v1 = val[s.y], v2 = val[s.z], v3 = val[s.w];
            atomicAdd(&acc[d.x], v0);
            atomicAdd(&acc[d.y], v1);
            atomicAdd(&acc[d.z], v2);
            atomicAdd(&acc[d.w], v3);
        } else {
            for (int e = base; e < E; e++) atomicAdd(&acc[dp[e]], val[sp[e]]);
        }
    } else {
        const long long* sp = (const long long*)ei;
        const long long* dp = sp + E;
        int end = min(base + 4, E);
        for (int e = base; e < end; e++)
            atomicAdd(&acc[(int)dp[e]], val[(int)sp[e]]);
    }
}

__global__ void k_scat1(const void* __restrict__ ei, int E) {
    scat2d(ei, E, g_xs, g_acc1);
}
__global__ void k_scat2(const void* __restrict__ ei, int E) {
    scat2d(ei, E, g_h2s, g_acc2);
}

// finalize layer 1: project aggregated 2-dim -> 16 -> relu -> @W2 -> pre-scale
__global__ void k_fin1(const float* __restrict__ W1,
                       const float* __restrict__ b1,
                       const float* __restrict__ W2, int n) {
    __shared__ float w1[32];   // [2,16] row-major
    __shared__ float w2[32];   // [16,2] row-major
    __shared__ float bb[F1];
    if (threadIdx.x < 32) { w1[threadIdx.x] = W1[threadIdx.x];
                            w2[threadIdx.x] = W2[threadIdx.x]; }
    if (threadIdx.x < F1)   bb[threadIdx.x] = b1[threadIdx.x];
    __syncthreads();
    int i = blockIdx.x * blockDim.x + threadIdx.x;
    if (i >= n) return;
    float di = g_dinv[i];
    float2 a  = g_acc1[i];
    float2 xs = g_xs[i];
    float t0 = di * (a.x + xs.x);
    float t1 = di * (a.y + xs.y);
    float o0 = 0.f, o1 = 0.f;
#pragma unroll
    for (int j = 0; j < F1; j++) {
        float r = fmaxf(t0 * w1[j] + t1 * w1[F1 + j] + bb[j], 0.f);
        o0 += r * w2[2 * j];
        o1 += r * w2[2 * j + 1];
    }
    g_h2s[i] = make_float2(di * o0, di * o1);
}

// finalize layer 2 + log_softmax, 2 nodes/thread
__global__ void k_fin2(const float* __restrict__ b2,
                       float* __restrict__ out, int n) {
    int t = blockIdx.x * blockDim.x + threadIdx.x;
    int i = t * 2;
    if (i >= n) return;
    float b0 = b2[0], b1v = b2[1];
    int cnt = (i + 2 <= n) ? 2 : 1;
#pragma unroll
    for (int k = 0; k < 2; k++) {
        if (k >= cnt) break;
        int j = i + k;
        float di = g_dinv[j];
        float2 a = g_acc2[j];
        float2 h = g_h2s[j];
        float o0 = di * (a.x + h.x) + b0;
        float o1 = di * (a.y + h.y) + b1v;
        float m = fmaxf(o0, o1);
        float lse = m + logf(expf(o0 - m) + expf(o1 - m));
        reinterpret_cast<float2*>(out)[j] = make_float2(o0 - lse, o1 - lse);
    }
}

extern "C" void kernel_launch(void* const* d_in, const int* in_sizes, int n_in,
                              void* d_out, int out_size) {
    const float* x  = (const float*)d_in[0];
    const void*  ei = d_in[1];
    const float* W1 = (const float*)d_in[2];
    const float* b1 = (const float*)d_in[3];
    const float* W2 = (const float*)d_in[4];
    const float* b2 = (const float*)d_in[5];
    float*       out = (float*)d_out;

    int n = in_sizes[0] / 2;        // [n, 2]
    int E = in_sizes[1] / 2;        // [2, E]

    // zero accumulators + degree via async memset (capturable, no alloc)
    void *p_deg, *p_a1, *p_a2;
    cudaGetSymbolAddress(&p_deg, g_deg);
    cudaGetSymbolAddress(&p_a1,  g_acc1);
    cudaGetSymbolAddress(&p_a2,  g_acc2);
    cudaMemsetAsync(p_deg, 0, n * sizeof(float));
    cudaMemsetAsync(p_a1,  0, n * sizeof(float2));
    cudaMemsetAsync(p_a2,  0, n * sizeof(float2));

    const int TB = 256;
    int gn   = (n + TB - 1) / TB;
    int gn2  = ((n + 1) / 2 + TB - 1) / TB;
    int ge4  = ((E + 3) / 4 + TB - 1) / TB;

    k_detect<<<1, 256>>>((const unsigned int*)ei, in_sizes[1]);
    k_deg   <<<ge4, TB>>>(ei, E);
    k_pre   <<<gn2, TB>>>(x, n);
    k_scat1 <<<ge4, TB>>>(ei, E);
    k_fin1  <<<gn, TB>>>(W1, b1, W2, n);
    k_scat2 <<<ge4, TB>>>(ei, E);
    k_fin2  <<<gn2, TB>>>(b2, out, n);
}

// round 13
// speedup vs baseline: 1.0589x; 1.0384x over previous
#include <cuda_runtime.h>

// ---------------------------------------------------------------------------
// 2-layer GCN, normalization factored; aggregation in 2-dim feature space
// (Â(xW1) = (Âx)W1).  Edge passes at the verified L2 random-sector roofline:
// 4 edges/thread, int4 index loads, float2 vector REDs.
// 7 graph nodes total; all zero-init fused into the detect kernel.
// ---------------------------------------------------------------------------

#define N_MAX 100000
#define F1 16

__device__ float2 g_xs  [N_MAX];   // dinv[i] * x[i]
__device__ float2 g_acc1[N_MAX];   // layer-1 edge sum (2-dim space)
__device__ float2 g_h2s [N_MAX];   // dinv[i] * (relu(l1) @ W2)
__device__ float2 g_acc2[N_MAX];   // layer-2 edge sum
__device__ float  g_deg [N_MAX];   // edge-only degree (self-loop via +1)
__device__ float  g_dinv[N_MAX];
__device__ int    g_is64;          // 1 if edge_index is int64

// Zero-init (all blocks) + dtype probe (block 0).
// int64 indices < 1e5 -> every odd 32-bit word is 0.
__global__ void k_detect_zero(const unsigned int* __restrict__ w, int nwords,
                              int n) {
    int i = blockIdx.x * blockDim.x + threadIdx.x;
    if (i < n) {
        g_deg[i] = 0.0f;
        float2 z = make_float2(0.f, 0.f);
        g_acc1[i] = z;
        g_acc2[i] = z;
    }
    if (blockIdx.x == 0) {
        __shared__ int nz;
        if (threadIdx.x == 0) nz = 0;
        __syncthreads();
        for (int k = threadIdx.x; k < 4096; k += blockDim.x) {
            int idx = 2 * k + 1;
            if (idx < nwords && w[idx] != 0u) nz = 1;
        }
        __syncthreads();
        if (threadIdx.x == 0) g_is64 = (nz == 0);
    }
}

// degree count at targets, 4 edges/thread via int4
__global__ void k_deg(const void* __restrict__ ei, int E) {
    int t = blockIdx.x * blockDim.x + threadIdx.x;
    int base = t * 4;
    if (base >= E) return;
    if (!g_is64) {
        const int* dst = (const int*)ei + E;
        if (base + 4 <= E) {
            int4 d = *reinterpret_cast<const int4*>(dst + base);
            atomicAdd(&g_deg[d.x], 1.0f);
            atomicAdd(&g_deg[d.y], 1.0f);
            atomicAdd(&g_deg[d.z], 1.0f);
            atomicAdd(&g_deg[d.w], 1.0f);
        } else {
            for (int e = base; e < E; e++) atomicAdd(&g_deg[dst[e]], 1.0f);
        }
    } else {
        const long long* dst = (const long long*)ei + E;
        int end = min(base + 4, E);
        for (int e = base; e < end; e++) atomicAdd(&g_deg[(int)dst[e]], 1.0f);
    }
}

// dinv + pre-scaled features, 2 nodes/thread (float4 I/O)
__global__ void k_pre(const float* __restrict__ x, int n) {
    int t = blockIdx.x * blockDim.x + threadIdx.x;
    int i = t * 2;
    if (i >= n) return;
    if (i + 2 <= n) {
        float2 dg = *reinterpret_cast<const float2*>(g_deg + i);
        float d0 = rsqrtf(dg.x + 1.0f);        // +1 = self loop
        float d1 = rsqrtf(dg.y + 1.0f);
        *reinterpret_cast<float2*>(g_dinv + i) = make_float2(d0, d1);
        float4 xv = *reinterpret_cast<const float4*>(x + i * 2);
        float4 o = make_float4(d0 * xv.x, d0 * xv.y, d1 * xv.z, d1 * xv.w);
        *reinterpret_cast<float4*>(&g_xs[i]) = o;
    } else {
        float di = rsqrtf(g_deg[i] + 1.0f);
        g_dinv[i] = di;
        float2 xv = reinterpret_cast<const float2*>(x)[i];
        g_xs[i] = make_float2(di * xv.x, di * xv.y);
    }
}

// 2-dim scatter: acc[dst] += val[src], 4 edges/thread (proven best config)
__device__ __forceinline__ void scat2d(const void* ei, int E,
                                       const float2* __restrict__ val,
                                       float2* __restrict__ acc) {
    int t = blockIdx.x * blockDim.x + threadIdx.x;
    int base = t * 4;
    if (base >= E) return;
    if (!g_is64) {
        const int* sp = (const int*)ei;
        const int* dp = sp + E;
        if (base + 4 <= E) {
            int4 s = *reinterpret_cast<const int4*>(sp + base);
            int4 d = *reinterpret_cast<const int4*>(dp + base);
            float2 v0 = val[s.x], v1 = val[s.y], v2 = val[s.z], v3 = val[s.w];
            atomicAdd(&acc[d.x], v0);
            atomicAdd(&acc[d.y], v1);
            atomicAdd(&acc[d.z], v2);
            atomicAdd(&acc[d.w], v3);
        } else {
            for (int e = base; e < E; e++) atomicAdd(&acc[dp[e]], val[sp[e]]);
        }
    } else {
        const long long* sp = (const long long*)ei;
        const long long* dp = sp + E;
        int end = min(base + 4, E);
        for (int e = base; e < end; e++)
            atomicAdd(&acc[(int)dp[e]], val[(int)sp[e]]);
    }
}

__global__ void k_scat1(const void* __restrict__ ei, int E) {
    scat2d(ei, E, g_xs, g_acc1);
}
__global__ void k_scat2(const void* __restrict__ ei, int E) {
    scat2d(ei, E, g_h2s, g_acc2);
}

// finalize layer 1: project aggregated 2-dim -> 16 -> relu -> @W2 -> pre-scale
__global__ void k_fin1(const float* __restrict__ W1,
                       const float* __restrict__ b1,
                       const float* __restrict__ W2, int n) {
    __shared__ float w1[32];   // [2,16] row-major
    __shared__ float w2[32];   // [16,2] row-major
    __shared__ float bb[F1];
    if (threadIdx.x < 32) { w1[threadIdx.x] = W1[threadIdx.x];
                            w2[threadIdx.x] = W2[threadIdx.x]; }
    if (threadIdx.x < F1)   bb[threadIdx.x] = b1[threadIdx.x];
    __syncthreads();
    int i = blockIdx.x * blockDim.x + threadIdx.x;
    if (i >= n) return;
    float di = g_dinv[i];
    float2 a  = g_acc1[i];
    float2 xs = g_xs[i];
    float t0 = di * (a.x + xs.x);
    float t1 = di * (a.y + xs.y);
    float o0 = 0.f, o1 = 0.f;
#pragma unroll
    for (int j = 0; j < F1; j++) {
        float r = fmaxf(t0 * w1[j] + t1 * w1[F1 + j] + bb[j], 0.f);
        o0 += r * w2[2 * j];
        o1 += r * w2[2 * j + 1];
    }
    g_h2s[i] = make_float2(di * o0, di * o1);
}

// finalize layer 2 + log_softmax, 2 nodes/thread
__global__ void k_fin2(const float* __restrict__ b2,
                       float* __restrict__ out, int n) {
    int t = blockIdx.x * blockDim.x + threadIdx.x;
    int i = t * 2;
    if (i >= n) return;
    float b0 = b2[0], b1v = b2[1];
    int cnt = (i + 2 <= n) ? 2 : 1;
#pragma unroll
    for (int k = 0; k < 2; k++) {
        if (k >= cnt) break;
        int j = i + k;
        float di = g_dinv[j];
        float2 a = g_acc2[j];
        float2 h = g_h2s[j];
        float o0 = di * (a.x + h.x) + b0;
        float o1 = di * (a.y + h.y) + b1v;
        float m = fmaxf(o0, o1);
        float lse = m + logf(expf(o0 - m) + expf(o1 - m));
        reinterpret_cast<float2*>(out)[j] = make_float2(o0 - lse, o1 - lse);
    }
}

extern "C" void kernel_launch(void* const* d_in, const int* in_sizes, int n_in,
                              void* d_out, int out_size) {
    const float* x  = (const float*)d_in[0];
    const void*  ei = d_in[1];
    const float* W1 = (const float*)d_in[2];
    const float* b1 = (const float*)d_in[3];
    const float* W2 = (const float*)d_in[4];
    const float* b2 = (const float*)d_in[5];
    float*       out = (float*)d_out;

    int n = in_sizes[0] / 2;        // [n, 2]
    int E = in_sizes[1] / 2;        // [2, E]

    const int TB = 256;
    int gn  = (n + TB - 1) / TB;
    int gn2 = ((n + 1) / 2 + TB - 1) / TB;
    int ge4 = ((E + 3) / 4 + TB - 1) / TB;

    k_detect_zero<<<gn, TB>>>((const unsigned int*)ei, in_sizes[1], n);
    k_deg  <<<ge4, TB>>>(ei, E);
    k_pre  <<<gn2, TB>>>(x, n);
    k_scat1<<<ge4, TB>>>(ei, E);
    k_fin1 <<<gn, TB>>>(W1, b1, W2, n);
    k_scat2<<<ge4, TB>>>(ei, E);
    k_fin2 <<<gn2, TB>>>(b2, out, n);
}